// round 2
// baseline (speedup 1.0000x reference)
#include <cuda_runtime.h>
#include <cuda_bf16.h>
#include <math.h>

// Problem constants
#define BB 16
#define SS 512
#define DD 128
#define HH 8
#define NC 4
#define KK 7
#define DK 16
#define NTOK (BB*SS)          // 8192
#define NELEM (BB*SS*DD)      // 1048576
#define LN_EPS 1e-5f

// ---------------------------------------------------------------------------
// Scratch (no allocation allowed -> __device__ globals)
// ---------------------------------------------------------------------------
__device__ float g_a[NELEM];        // ping
__device__ float g_b[NELEM];        // pong
__device__ float g_q[NELEM];
__device__ float g_k[NELEM];
__device__ float g_v[NELEM];
__device__ float g_t[NELEM];
__device__ float g_wq[DD*DD];
__device__ float g_wk[DD*DD];
__device__ float g_wv[DD*DD];
__device__ float g_wpw[NC*DD*DD];
__device__ float g_wf1[DD*DD];
__device__ float g_wf2[DD*DD];

// ---------------------------------------------------------------------------
// Weight repacks (canonical [k_in][n_out])
// ---------------------------------------------------------------------------
__global__ void repack_qkv_kernel(const float* __restrict__ Wq,
                                  const float* __restrict__ Wk,
                                  const float* __restrict__ Wv) {
    int i = blockIdx.x * 256 + threadIdx.x;
    if (i >= DD*DD) return;
    int d = i >> 7, c = i & 127;
    int h = c >> 4, kk = c & 15;
    int si = (h*DD + d)*DK + kk;
    g_wq[i] = Wq[si];
    g_wk[i] = Wk[si];
    g_wv[i] = Wv[si];
}

// pw_w shape (NC, D_out, D_in, 1): dst[l][din*128+dout] = pw[(l*128+dout)*128+din]
__global__ void repack_pw_kernel(const float* __restrict__ pw) {
    int i = blockIdx.x * 256 + threadIdx.x;
    if (i >= NC*DD*DD) return;
    int l = i >> 14;
    int r = i & 16383;
    int din = r >> 7, dout = r & 127;
    g_wpw[i] = pw[(l*DD + dout)*DD + din];
}

// f1_w, f2_w shape (D_out, D_in); used as h @ W.T -> dst[din*128+dout] = W[dout*128+din]
__global__ void repack_ffn_kernel(const float* __restrict__ f1,
                                  const float* __restrict__ f2) {
    int i = blockIdx.x * 256 + threadIdx.x;
    if (i >= DD*DD) return;
    int d = i >> 7, c = i & 127;
    g_wf1[i] = f1[c*DD + d];
    g_wf2[i] = f2[c*DD + d];
}

// ---------------------------------------------------------------------------
// out = x + positional signal  (first 64 channels sin, last 64 cos)
// ---------------------------------------------------------------------------
__global__ void pos_add_kernel(const float* __restrict__ x, float* __restrict__ out) {
    int idx = blockIdx.x * 256 + threadIdx.x;
    if (idx >= NELEM) return;
    int d = idx & 127;
    int s = (idx >> 7) & (SS - 1);
    const float inc = 9.210340371976184f / 63.0f;   // ln(10000)/(nt-1)
    float p;
    if (d < 64) {
        float inv = __expf(-(float)d * inc);
        p = sinf((float)s * inv);
    } else {
        float inv = __expf(-(float)(d - 64) * inc);
        p = cosf((float)s * inv);
    }
    out[idx] = x[idx] + p;
}

// ---------------------------------------------------------------------------
// Fused conv block: LN -> depthwise(7) -> pointwise GEMM (+bias,relu) -> +residual
// One block = 64 tokens (never straddles a batch: 512 % 64 == 0).
// Reads IN (prev activations), writes OUT (different buffer -> no races).
// Dynamic smem: Rs[70][132] raw rows (halo +-3), Xs[64][132] conv result,
//               mu[70], rstd[70].
// ---------------------------------------------------------------------------
__global__ void __launch_bounds__(256) conv_fused_kernel(
        const float* __restrict__ IN,
        const float* __restrict__ gam, const float* __restrict__ bet,
        const float* __restrict__ dww,  // [D][7]
        const float* __restrict__ dwb,  // [D]
        const float* __restrict__ W,    // pointwise canonical [din][dout]
        const float* __restrict__ pwb,  // [D]
        float* __restrict__ OUT) {
    extern __shared__ float sm[];
    float* Rs   = sm;                    // 70*132
    float* Xs   = sm + 70*132;           // 64*132
    float* mu_s = sm + 70*132 + 64*132;  // 70
    float* rs_s = mu_s + 70;             // 70

    int tid = threadIdx.x;
    int row0 = blockIdx.x * 64;          // global token of first center row
    int s0 = row0 & (SS - 1);            // position within batch
    int bstart = row0 - s0;              // first token of this batch

    // 1) load 70 raw rows (halo), zero outside the sequence
    for (int li = tid; li < 70*128; li += 256) {
        int r = li >> 7, c = li & 127;
        int spos = s0 + r - 3;
        float v = 0.f;
        if (spos >= 0 && spos < SS)
            v = IN[(size_t)(bstart + spos)*DD + c];
        Rs[r*132 + c] = v;
    }
    __syncthreads();

    // 2) LN stats per row (warp per row, strided)
    {
        int warp = tid >> 5, lane = tid & 31;
        for (int r = warp; r < 70; r += 8) {
            float v0 = Rs[r*132 + lane];
            float v1 = Rs[r*132 + lane + 32];
            float v2 = Rs[r*132 + lane + 64];
            float v3 = Rs[r*132 + lane + 96];
            float s = v0 + v1 + v2 + v3;
#pragma unroll
            for (int off = 16; off; off >>= 1) s += __shfl_xor_sync(0xffffffffu, s, off);
            float mu = s * (1.0f/128.0f);
            float d0 = v0-mu, d1 = v1-mu, d2 = v2-mu, d3 = v3-mu;
            float q = d0*d0 + d1*d1 + d2*d2 + d3*d3;
#pragma unroll
            for (int off = 16; off; off >>= 1) q += __shfl_xor_sync(0xffffffffu, q, off);
            if (lane == 0) {
                mu_s[r] = mu;
                rs_s[r] = rsqrtf(q * (1.0f/128.0f) + LN_EPS);
            }
        }
    }
    __syncthreads();

    // 3) depthwise conv with LN applied inline (zero-pad outside sequence)
    for (int li = tid; li < 64*128; li += 256) {
        int r = li >> 7, c = li & 127;
        float gc = __ldg(gam + c), bc = __ldg(bet + c);
        float acc = __ldg(dwb + c);
        const float* wp = dww + c*KK;
#pragma unroll
        for (int j = 0; j < KK; j++) {
            int rr = r + j;              // halo row index (center = r+3 at j=3)
            int spos = s0 + r + j - 3;
            if (spos >= 0 && spos < SS) {
                float xv = (Rs[rr*132 + c] - mu_s[rr]) * rs_s[rr];
                float nv = xv * gc + bc;
                acc = fmaf(nv, __ldg(wp + j), acc);
            }
        }
        Xs[r*132 + c] = acc;
    }
    __syncthreads();

    // 4) pointwise GEMM 64x128x128, epilogue relu(+bias) + residual(Rs center)
    int ty = tid >> 4, tx = tid & 15;
    int r0 = ty * 4, c0 = tx * 8;
    float acc[4][8];
#pragma unroll
    for (int i = 0; i < 4; i++)
#pragma unroll
        for (int j = 0; j < 8; j++) acc[i][j] = 0.f;
    const float* Wp = W + c0;
#pragma unroll 8
    for (int kk = 0; kk < 128; kk++) {
        float4 w0 = __ldg((const float4*)(Wp + kk*128));
        float4 w1 = __ldg((const float4*)(Wp + kk*128 + 4));
        float wv[8] = {w0.x, w0.y, w0.z, w0.w, w1.x, w1.y, w1.z, w1.w};
#pragma unroll
        for (int i = 0; i < 4; i++) {
            float xv = Xs[(r0 + i)*132 + kk];
#pragma unroll
            for (int j = 0; j < 8; j++) acc[i][j] = fmaf(xv, wv[j], acc[i][j]);
        }
    }
    float bv[8];
#pragma unroll
    for (int j = 0; j < 8; j++) bv[j] = __ldg(pwb + c0 + j);
#pragma unroll
    for (int i = 0; i < 4; i++) {
        int row = row0 + r0 + i;
#pragma unroll
        for (int j = 0; j < 8; j++) {
            float v = fmaxf(acc[i][j] + bv[j], 0.f);
            v += Rs[(r0 + i + 3)*132 + c0 + j];     // residual = raw input row
            OUT[(size_t)row*DD + c0 + j] = v;
        }
    }
}

// ---------------------------------------------------------------------------
// GEMM with fused LN prologue. Y = act(LN(X) @ W + bias + scalar)
// 64-row tile, 256 threads, 4x8 micro-tile.
// ---------------------------------------------------------------------------
__device__ __forceinline__ void ln_tile_load(const float* __restrict__ X,
                                             const float* __restrict__ gam,
                                             const float* __restrict__ bet,
                                             float* Xs, int row0, int tid) {
    // 4 threads per row, 32 cols each
    int r = tid >> 2, sub = tid & 3;
    const float* xp = X + (size_t)(row0 + r)*DD + sub*32;
    float v[32];
    float s = 0.f;
#pragma unroll
    for (int j = 0; j < 8; j++) {
        float4 t4 = __ldg((const float4*)(xp + j*4));
        v[4*j+0]=t4.x; v[4*j+1]=t4.y; v[4*j+2]=t4.z; v[4*j+3]=t4.w;
        s += t4.x + t4.y + t4.z + t4.w;
    }
    s += __shfl_xor_sync(0xffffffffu, s, 1);
    s += __shfl_xor_sync(0xffffffffu, s, 2);
    float mu = s * (1.0f/128.0f);
    float q = 0.f;
#pragma unroll
    for (int j = 0; j < 32; j++) { float d = v[j]-mu; q += d*d; }
    q += __shfl_xor_sync(0xffffffffu, q, 1);
    q += __shfl_xor_sync(0xffffffffu, q, 2);
    float rstd = rsqrtf(q * (1.0f/128.0f) + LN_EPS);
#pragma unroll
    for (int j = 0; j < 32; j++) {
        int c = sub*32 + j;
        Xs[r*132 + c] = (v[j]-mu)*rstd*__ldg(gam+c) + __ldg(bet+c);
    }
}

__device__ __forceinline__ void gemm_core(const float* Xs, const float* __restrict__ W,
                                          int r0, int c0, float acc[4][8]) {
#pragma unroll
    for (int i = 0; i < 4; i++)
#pragma unroll
        for (int j = 0; j < 8; j++) acc[i][j] = 0.f;
    const float* Wp = W + c0;
#pragma unroll 8
    for (int kk = 0; kk < 128; kk++) {
        float4 w0 = __ldg((const float4*)(Wp + kk*128));
        float4 w1 = __ldg((const float4*)(Wp + kk*128 + 4));
        float wv[8] = {w0.x, w0.y, w0.z, w0.w, w1.x, w1.y, w1.z, w1.w};
#pragma unroll
        for (int i = 0; i < 4; i++) {
            float xv = Xs[(r0 + i)*132 + kk];
#pragma unroll
            for (int j = 0; j < 8; j++) acc[i][j] = fmaf(xv, wv[j], acc[i][j]);
        }
    }
}

// Q,K,V in one pass: LN tile once, 3 weight passes (+att_bias scalar)
__global__ void __launch_bounds__(256) gemm_qkv_ln_kernel(
        const float* __restrict__ X,
        const float* __restrict__ gam, const float* __restrict__ bet,
        const float* __restrict__ attb,
        float* __restrict__ Q, float* __restrict__ K, float* __restrict__ V) {
    __shared__ float Xs[64*132];
    int tid = threadIdx.x;
    int row0 = blockIdx.x * 64;
    ln_tile_load(X, gam, bet, Xs, row0, tid);
    __syncthreads();
    int ty = tid >> 4, tx = tid & 15;
    int r0 = ty*4, c0 = tx*8;
    float sc = __ldg(attb);
    float acc[4][8];

    const float* Ws[3] = {g_wq, g_wk, g_wv};
    float* Ys[3] = {Q, K, V};
#pragma unroll
    for (int m = 0; m < 3; m++) {
        gemm_core(Xs, Ws[m], r0, c0, acc);
#pragma unroll
        for (int i = 0; i < 4; i++) {
            int row = row0 + r0 + i;
#pragma unroll
            for (int j = 0; j < 8; j++)
                Ys[m][(size_t)row*DD + c0 + j] = acc[i][j] + sc;
        }
    }
}

// LN + GEMM, relu + bias (FFN first layer)
__global__ void __launch_bounds__(256) gemm_ln_relu_kernel(
        const float* __restrict__ X,
        const float* __restrict__ gam, const float* __restrict__ bet,
        const float* __restrict__ W, const float* __restrict__ bias,
        float* __restrict__ Y) {
    __shared__ float Xs[64*132];
    int tid = threadIdx.x;
    int row0 = blockIdx.x * 64;
    ln_tile_load(X, gam, bet, Xs, row0, tid);
    __syncthreads();
    int ty = tid >> 4, tx = tid & 15;
    int r0 = ty*4, c0 = tx*8;
    float acc[4][8];
    gemm_core(Xs, W, r0, c0, acc);
    float bv[8];
#pragma unroll
    for (int j = 0; j < 8; j++) bv[j] = __ldg(bias + c0 + j);
#pragma unroll
    for (int i = 0; i < 4; i++) {
        int row = row0 + r0 + i;
#pragma unroll
        for (int j = 0; j < 8; j++)
            Y[(size_t)row*DD + c0 + j] = fmaxf(acc[i][j] + bv[j], 0.f);
    }
}

// Plain GEMM: Y = X@W + bias? + scalar? + resid?
__global__ void __launch_bounds__(256) gemm_kernel(
        const float* __restrict__ X, const float* __restrict__ W,
        float* __restrict__ Y,
        const float* __restrict__ bias, const float* __restrict__ resid,
        const float* __restrict__ scalar_ptr) {
    __shared__ float Xs[64*132];
    int tid = threadIdx.x;
    int row0 = blockIdx.x * 64;
#pragma unroll
    for (int i = 0; i < 32; i++) {
        int li = tid + i*256;
        int r = li >> 7, c = li & 127;
        Xs[r*132 + c] = X[(size_t)(row0 + r)*DD + c];
    }
    __syncthreads();
    int ty = tid >> 4, tx = tid & 15;
    int r0 = ty*4, c0 = tx*8;
    float acc[4][8];
    gemm_core(Xs, W, r0, c0, acc);
    float sc = scalar_ptr ? __ldg(scalar_ptr) : 0.f;
    float bv[8];
#pragma unroll
    for (int j = 0; j < 8; j++) bv[j] = bias ? __ldg(bias + c0 + j) : 0.f;
#pragma unroll
    for (int i = 0; i < 4; i++) {
        int row = row0 + r0 + i;
#pragma unroll
        for (int j = 0; j < 8; j++) {
            float v = acc[i][j] + sc + bv[j];
            if (resid) v += resid[(size_t)row*DD + c0 + j];
            Y[(size_t)row*DD + c0 + j] = v;
        }
    }
}

// ---------------------------------------------------------------------------
// Attention: one block per (b,h); 512 threads = 1 thread per query.
// ---------------------------------------------------------------------------
__global__ void __launch_bounds__(512) attn_kernel(const float* __restrict__ Q,
                                                   const float* __restrict__ Kg,
                                                   const float* __restrict__ Vg,
                                                   const int* __restrict__ mask,
                                                   float* __restrict__ Out) {
    extern __shared__ float sm[];
    float* Ksm = sm;                 // 512*16
    float* Vsm = sm + SS*DK;         // 512*16
    float* Msm = sm + 2*SS*DK;       // 512

    int b = blockIdx.x >> 3;
    int h = blockIdx.x & 7;
    int tid = threadIdx.x;

    for (int i = tid; i < SS*DK; i += 512) {
        int t = i >> 4, kk = i & 15;
        size_t gi = ((size_t)(b*SS + t))*DD + h*DK + kk;
        Ksm[i] = Kg[gi];
        Vsm[i] = Vg[gi];
    }
    Msm[tid] = (float)mask[b*SS + tid];
    __syncthreads();

    float q[16];
    {
        const float4* qp = (const float4*)(Q + ((size_t)(b*SS + tid))*DD + h*DK);
#pragma unroll
        for (int j = 0; j < 4; j++) {
            float4 t4 = qp[j];
            q[4*j+0]=t4.x; q[4*j+1]=t4.y; q[4*j+2]=t4.z; q[4*j+3]=t4.w;
        }
    }

    float mval = -1e30f, lsum = 0.f;
    float acc[16];
#pragma unroll
    for (int j = 0; j < 16; j++) acc[j] = 0.f;

    const float4* K4 = (const float4*)Ksm;
    const float4* V4 = (const float4*)Vsm;
    for (int t = 0; t < SS; t++) {
        float4 k0 = K4[t*4+0], k1 = K4[t*4+1], k2 = K4[t*4+2], k3 = K4[t*4+3];
        float s =  q[0]*k0.x + q[1]*k0.y + q[2]*k0.z + q[3]*k0.w
                 + q[4]*k1.x + q[5]*k1.y + q[6]*k1.z + q[7]*k1.w
                 + q[8]*k2.x + q[9]*k2.y + q[10]*k2.z + q[11]*k2.w
                 + q[12]*k3.x + q[13]*k3.y + q[14]*k3.z + q[15]*k3.w;
        s *= 0.25f;                                  // 1/sqrt(16)
        float fm = Msm[t];
        s = fm * s + (1.0f - fm) * (-1e30f);
        float mnew = fmaxf(mval, s);
        float corr = __expf(mval - mnew);
        float p = __expf(s - mnew);
        mval = mnew;
        lsum = lsum * corr + p;
        float4 v0 = V4[t*4+0], v1 = V4[t*4+1], v2 = V4[t*4+2], v3 = V4[t*4+3];
        acc[0]  = acc[0]*corr  + p*v0.x;  acc[1]  = acc[1]*corr  + p*v0.y;
        acc[2]  = acc[2]*corr  + p*v0.z;  acc[3]  = acc[3]*corr  + p*v0.w;
        acc[4]  = acc[4]*corr  + p*v1.x;  acc[5]  = acc[5]*corr  + p*v1.y;
        acc[6]  = acc[6]*corr  + p*v1.z;  acc[7]  = acc[7]*corr  + p*v1.w;
        acc[8]  = acc[8]*corr  + p*v2.x;  acc[9]  = acc[9]*corr  + p*v2.y;
        acc[10] = acc[10]*corr + p*v2.z;  acc[11] = acc[11]*corr + p*v2.w;
        acc[12] = acc[12]*corr + p*v3.x;  acc[13] = acc[13]*corr + p*v3.y;
        acc[14] = acc[14]*corr + p*v3.z;  acc[15] = acc[15]*corr + p*v3.w;
    }
    float inv_l = 1.0f / lsum;
    float* op = Out + ((size_t)(b*SS + tid))*DD + h*DK;
#pragma unroll
    for (int j = 0; j < 16; j++) op[j] = acc[j] * inv_l;
}

// ---------------------------------------------------------------------------
// Host launcher
// ---------------------------------------------------------------------------
extern "C" void kernel_launch(void* const* d_in, const int* in_sizes, int n_in,
                              void* d_out, int out_size) {
    const float* x     = (const float*)d_in[0];
    const int*   mask  = (const int*)  d_in[1];
    const float* ln_s  = (const float*)d_in[2];
    const float* ln_b  = (const float*)d_in[3];
    const float* dw_w  = (const float*)d_in[4];
    const float* dw_b  = (const float*)d_in[5];
    const float* pw_w  = (const float*)d_in[6];
    const float* pw_b  = (const float*)d_in[7];
    const float* Wq    = (const float*)d_in[8];
    const float* Wk    = (const float*)d_in[9];
    const float* Wv    = (const float*)d_in[10];
    const float* Wo    = (const float*)d_in[11];
    const float* attb  = (const float*)d_in[12];
    const float* f1w   = (const float*)d_in[13];
    const float* f1b   = (const float*)d_in[14];
    const float* f2w   = (const float*)d_in[15];
    const float* f2b   = (const float*)d_in[16];
    float* out = (float*)d_out;

    float *p_a, *p_b, *p_q, *p_k, *p_v, *p_t;
    float *p_wpw, *p_wf1, *p_wf2;
    cudaGetSymbolAddress((void**)&p_a,   g_a);
    cudaGetSymbolAddress((void**)&p_b,   g_b);
    cudaGetSymbolAddress((void**)&p_q,   g_q);
    cudaGetSymbolAddress((void**)&p_k,   g_k);
    cudaGetSymbolAddress((void**)&p_v,   g_v);
    cudaGetSymbolAddress((void**)&p_t,   g_t);
    cudaGetSymbolAddress((void**)&p_wpw, g_wpw);
    cudaGetSymbolAddress((void**)&p_wf1, g_wf1);
    cudaGetSymbolAddress((void**)&p_wf2, g_wf2);

    const int conv_smem = (70*132 + 64*132 + 140) * (int)sizeof(float); // ~71.3 KB
    const int attn_smem = (2*SS*DK + SS) * (int)sizeof(float);          // 67.6 KB
    cudaFuncSetAttribute(conv_fused_kernel, cudaFuncAttributeMaxDynamicSharedMemorySize, conv_smem);
    cudaFuncSetAttribute(attn_kernel, cudaFuncAttributeMaxDynamicSharedMemorySize, attn_smem);

    // weight repacks (cheap)
    repack_qkv_kernel<<<(DD*DD + 255)/256, 256>>>(Wq, Wk, Wv);
    repack_pw_kernel <<<(NC*DD*DD + 255)/256, 256>>>(pw_w);
    repack_ffn_kernel<<<(DD*DD + 255)/256, 256>>>(f1w, f2w);

    // out = x + pos_signal  -> g_a
    pos_add_kernel<<<NELEM/256, 256>>>(x, p_a);

    // 4 fused conv blocks, ping-pong a->b->a->b->a
    float* bufs[2] = {p_a, p_b};
    for (int i = 0; i < NC; i++) {
        conv_fused_kernel<<<NTOK/64, 256, conv_smem>>>(
            bufs[i & 1], ln_s + i*DD, ln_b + i*DD,
            dw_w + i*DD*KK, dw_b + i*DD,
            p_wpw + i*DD*DD, pw_b + i*DD,
            bufs[(i + 1) & 1]);
    }
    float* cur = bufs[NC & 1];   // = p_a

    // attention: fused LN + QKV
    gemm_qkv_ln_kernel<<<NTOK/64, 256>>>(cur, ln_s + NC*DD, ln_b + NC*DD,
                                         attb, p_q, p_k, p_v);
    attn_kernel<<<BB*HH, 512, attn_smem>>>(p_q, p_k, p_v, mask, p_t);
    // out = mh @ Wo + b0 + residual(cur)  (in-place on cur is safe: same-thread RMW)
    gemm_kernel<<<NTOK/64, 256>>>(p_t, Wo, cur, nullptr, cur, attb);

    // feed-forward: LN+f1(relu) -> f2 (+resid) -> d_out
    gemm_ln_relu_kernel<<<NTOK/64, 256>>>(cur, ln_s + (NC+1)*DD, ln_b + (NC+1)*DD,
                                          p_wf1, f1b, p_t);
    gemm_kernel<<<NTOK/64, 256>>>(p_t, p_wf2, out, f2b, cur, nullptr);

    (void)in_sizes; (void)n_in; (void)out_size;
}

// round 14
// speedup vs baseline: 1.1680x; 1.1680x over previous
#include <cuda_runtime.h>
#include <cuda_bf16.h>
#include <math.h>

// Problem constants
#define BB 16
#define SS 512
#define DD 128
#define HH 8
#define NC 4
#define KK 7
#define DK 16
#define NTOK (BB*SS)          // 8192
#define NELEM (BB*SS*DD)      // 1048576
#define LN_EPS 1e-5f

// ---------------------------------------------------------------------------
// f32x2 packed math helpers (FFMA2 path — PTX only, ptxas won't auto-fuse)
// ---------------------------------------------------------------------------
typedef unsigned long long u64;

__device__ __forceinline__ u64 fma2(u64 a, u64 b, u64 c) {
    u64 d;
    asm("fma.rn.f32x2 %0, %1, %2, %3;" : "=l"(d) : "l"(a), "l"(b), "l"(c));
    return d;
}
__device__ __forceinline__ u64 mul2(u64 a, u64 b) {
    u64 d;
    asm("mul.rn.f32x2 %0, %1, %2;" : "=l"(d) : "l"(a), "l"(b));
    return d;
}
__device__ __forceinline__ u64 pack2(float x, float y) {
    u64 d;
    asm("mov.b64 %0, {%1, %2};" : "=l"(d) : "f"(x), "f"(y));
    return d;
}
__device__ __forceinline__ u64 pack2dup(float x) {
    u64 d;
    asm("mov.b64 %0, {%1, %1};" : "=l"(d) : "f"(x));
    return d;
}
__device__ __forceinline__ float2 unpack2(u64 v) {
    float2 r;
    asm("mov.b64 {%0, %1}, %2;" : "=f"(r.x), "=f"(r.y) : "l"(v));
    return r;
}

// ---------------------------------------------------------------------------
// Scratch (no allocation allowed -> __device__ globals).
// __align__(256): gemm_tile2 does 16B vector loads from the weight arrays.
// ---------------------------------------------------------------------------
__device__ __align__(256) float g_a[NELEM];        // ping
__device__ __align__(256) float g_b[NELEM];        // pong
__device__ __align__(256) float g_q[NELEM];
__device__ __align__(256) float g_k[NELEM];
__device__ __align__(256) float g_v[NELEM];
__device__ __align__(256) float g_t[NELEM];
__device__ __align__(256) float g_wq[DD*DD];
__device__ __align__(256) float g_wk[DD*DD];
__device__ __align__(256) float g_wv[DD*DD];
__device__ __align__(256) float g_wpw[NC*DD*DD];
__device__ __align__(256) float g_wf1[DD*DD];
__device__ __align__(256) float g_wf2[DD*DD];

// ---------------------------------------------------------------------------
// Single repack kernel (canonical [k_in][n_out] for all weight matrices)
// ---------------------------------------------------------------------------
__global__ void repack_all_kernel(const float* __restrict__ Wq,
                                  const float* __restrict__ Wk,
                                  const float* __restrict__ Wv,
                                  const float* __restrict__ pw,
                                  const float* __restrict__ f1,
                                  const float* __restrict__ f2) {
    int i = blockIdx.x * 256 + threadIdx.x;
    if (i < DD*DD) {
        int d = i >> 7, c = i & 127;
        int h = c >> 4, kk = c & 15;
        int si = (h*DD + d)*DK + kk;
        g_wq[i] = Wq[si];
        g_wk[i] = Wk[si];
        g_wv[i] = Wv[si];
        g_wf1[i] = f1[c*DD + d];
        g_wf2[i] = f2[c*DD + d];
    }
    if (i < NC*DD*DD) {
        int l = i >> 14;
        int r = i & 16383;
        int din = r >> 7, dout = r & 127;
        g_wpw[i] = pw[(l*DD + dout)*DD + din];
    }
}

// ---------------------------------------------------------------------------
// positional signal (first 64 channels sin, last 64 cos)
// ---------------------------------------------------------------------------
__device__ __forceinline__ float possig(int s, int d) {
    const float inc = 9.210340371976184f / 63.0f;   // ln(10000)/(nt-1)
    float dd = (d < 64) ? (float)d : (float)(d - 64);
    float inv = __expf(-dd * inc);
    float arg = (float)s * inv;
    return (d < 64) ? sinf(arg) : cosf(arg);
}

// ---------------------------------------------------------------------------
// f32x2 GEMM tile core: 64 rows x 128 cols, 256 threads, 4x8 micro-tile.
// Xs2: smem [64][132] of DUPLICATED (x,x) 8-byte pairs -> LDS.64 delivers the
// packed operand directly (no pack2dup in the inner loop).
// W: global canonical [k=128][n=128] (64KB, L1-resident after first pass).
// Issue budget/k/thread: 4 LDS.64 + 2 LDG.128 + 16 FFMA2.
// ---------------------------------------------------------------------------
__device__ __forceinline__ void gemm_tile2(const u64* Xs2, const float* __restrict__ W,
                                           int r0, int c0, float acc[4][8]) {
    u64 a2[4][4];
#pragma unroll
    for (int i = 0; i < 4; i++)
#pragma unroll
        for (int j = 0; j < 4; j++) a2[i][j] = 0ull;   // (+0.f, +0.f)
    const float* Wp = W + c0;
#pragma unroll 8
    for (int kk = 0; kk < 128; kk++) {
        ulonglong2 wa = *(const ulonglong2*)(Wp + (size_t)kk*128);
        ulonglong2 wb = *(const ulonglong2*)(Wp + (size_t)kk*128 + 4);
        u64 x0 = Xs2[(r0 + 0)*132 + kk];
        u64 x1 = Xs2[(r0 + 1)*132 + kk];
        u64 x2 = Xs2[(r0 + 2)*132 + kk];
        u64 x3 = Xs2[(r0 + 3)*132 + kk];
        a2[0][0] = fma2(x0, wa.x, a2[0][0]);
        a2[0][1] = fma2(x0, wa.y, a2[0][1]);
        a2[0][2] = fma2(x0, wb.x, a2[0][2]);
        a2[0][3] = fma2(x0, wb.y, a2[0][3]);
        a2[1][0] = fma2(x1, wa.x, a2[1][0]);
        a2[1][1] = fma2(x1, wa.y, a2[1][1]);
        a2[1][2] = fma2(x1, wb.x, a2[1][2]);
        a2[1][3] = fma2(x1, wb.y, a2[1][3]);
        a2[2][0] = fma2(x2, wa.x, a2[2][0]);
        a2[2][1] = fma2(x2, wa.y, a2[2][1]);
        a2[2][2] = fma2(x2, wb.x, a2[2][2]);
        a2[2][3] = fma2(x2, wb.y, a2[2][3]);
        a2[3][0] = fma2(x3, wa.x, a2[3][0]);
        a2[3][1] = fma2(x3, wa.y, a2[3][1]);
        a2[3][2] = fma2(x3, wb.x, a2[3][2]);
        a2[3][3] = fma2(x3, wb.y, a2[3][3]);
    }
#pragma unroll
    for (int i = 0; i < 4; i++)
#pragma unroll
        for (int j = 0; j < 4; j++) {
            float2 t = unpack2(a2[i][j]);
            acc[i][2*j+0] = t.x;
            acc[i][2*j+1] = t.y;
        }
}

// ---------------------------------------------------------------------------
// Fused conv block: [pos?] -> LN -> depthwise(7) -> pointwise GEMM(+bias,relu)
//                   -> +residual.  One block = 64 tokens (tiles never straddle
//                   a batch: 512 % 64 == 0).
// dyn smem layout (bytes):
//   [0, 67584)        Xs2  u64[64*132]   duplicated conv output (GEMM input)
//   [67584, 104544)   Rs   f32[70*132]   raw(+pos) rows with halo
//   [104544, 141504)  Ns   f32[70*132]   normalized rows (zero outside seq)
//   [141504, 141784)  mu_s f32[70]
//   [141784, 142064)  rs_s f32[70]
// ---------------------------------------------------------------------------
#define CONV_SMEM 142064
__global__ void __launch_bounds__(256) conv_fused_kernel(
        const float* __restrict__ IN,
        const float* __restrict__ gam, const float* __restrict__ bet,
        const float* __restrict__ dww,  // [D][7]
        const float* __restrict__ dwb,  // [D]
        const float* __restrict__ W,    // pointwise canonical [din][dout]
        const float* __restrict__ pwb,  // [D]
        float* __restrict__ OUT,
        int add_pos) {
    extern __shared__ char smc[];
    u64*   Xs2  = (u64*)smc;
    float* Rs   = (float*)(smc + 67584);
    float* Ns   = (float*)(smc + 104544);
    float* mu_s = (float*)(smc + 141504);
    float* rs_s = (float*)(smc + 141784);

    int tid = threadIdx.x;
    int row0 = blockIdx.x * 64;
    int s0 = row0 & (SS - 1);
    int bstart = row0 - s0;

    // 1) load 70 raw rows (halo +-3), add pos signal if requested
    for (int li = tid; li < 70*128; li += 256) {
        int r = li >> 7, c = li & 127;
        int spos = s0 + r - 3;
        float v = 0.f;
        if (spos >= 0 && spos < SS) {
            v = IN[(size_t)(bstart + spos)*DD + c];
            if (add_pos) v += possig(spos, c);
        }
        Rs[r*132 + c] = v;
    }
    __syncthreads();

    // 2) LN stats per halo row (warp per row, strided; 8 warps cover 70 rows)
    {
        int warp = tid >> 5, lane = tid & 31;
        for (int r = warp; r < 70; r += 8) {
            float v0 = Rs[r*132 + lane];
            float v1 = Rs[r*132 + lane + 32];
            float v2 = Rs[r*132 + lane + 64];
            float v3 = Rs[r*132 + lane + 96];
            float s = v0 + v1 + v2 + v3;
#pragma unroll
            for (int off = 16; off; off >>= 1) s += __shfl_xor_sync(0xffffffffu, s, off);
            float mu = s * (1.0f/128.0f);
            float d0 = v0-mu, d1 = v1-mu, d2 = v2-mu, d3 = v3-mu;
            float q = d0*d0 + d1*d1 + d2*d2 + d3*d3;
#pragma unroll
            for (int off = 16; off; off >>= 1) q += __shfl_xor_sync(0xffffffffu, q, off);
            if (lane == 0) {
                mu_s[r] = mu;
                rs_s[r] = rsqrtf(q * (1.0f/128.0f) + LN_EPS);
            }
        }
    }
    __syncthreads();

    // 3) normalized rows (zero outside the sequence = conv zero-padding)
    for (int li = tid; li < 70*128; li += 256) {
        int r = li >> 7, c = li & 127;
        int spos = s0 + r - 3;
        float v = 0.f;
        if (spos >= 0 && spos < SS)
            v = (Rs[r*132 + c] - mu_s[r]) * rs_s[r] * __ldg(gam + c) + __ldg(bet + c);
        Ns[r*132 + c] = v;
    }
    __syncthreads();

    // 4) depthwise conv (pure 7-tap FMA), write duplicated for GEMM
    for (int li = tid; li < 64*128; li += 256) {
        int r = li >> 7, c = li & 127;
        const float* wp = dww + c*KK;
        float acc = __ldg(dwb + c);
#pragma unroll
        for (int j = 0; j < KK; j++)
            acc = fmaf(Ns[(r + j)*132 + c], __ldg(wp + j), acc);
        Xs2[r*132 + c] = pack2dup(acc);
    }
    __syncthreads();

    // 5) pointwise GEMM, epilogue relu(+bias) + residual (raw center rows)
    int ty = tid >> 4, tx = tid & 15;
    int r0 = ty * 4, c0 = tx * 8;
    float acc[4][8];
    gemm_tile2(Xs2, W, r0, c0, acc);
    float bv[8];
#pragma unroll
    for (int j = 0; j < 8; j++) bv[j] = __ldg(pwb + c0 + j);
#pragma unroll
    for (int i = 0; i < 4; i++) {
        int row = row0 + r0 + i;
#pragma unroll
        for (int j = 0; j < 8; j++) {
            float v = fmaxf(acc[i][j] + bv[j], 0.f);
            v += Rs[(r0 + i + 3)*132 + c0 + j];
            OUT[(size_t)row*DD + c0 + j] = v;
        }
    }
}

// ---------------------------------------------------------------------------
// LN tile prologue: 4 threads per row, 32 cols each -> duplicated Xs2[64][132]
// ---------------------------------------------------------------------------
__device__ __forceinline__ void ln_tile_load(const float* __restrict__ X,
                                             const float* __restrict__ gam,
                                             const float* __restrict__ bet,
                                             u64* Xs2, int row0, int tid) {
    int r = tid >> 2, sub = tid & 3;
    const float* xp = X + (size_t)(row0 + r)*DD + sub*32;
    float v[32];
    float s = 0.f;
#pragma unroll
    for (int j = 0; j < 8; j++) {
        float4 t4 = __ldg((const float4*)(xp + j*4));
        v[4*j+0]=t4.x; v[4*j+1]=t4.y; v[4*j+2]=t4.z; v[4*j+3]=t4.w;
        s += t4.x + t4.y + t4.z + t4.w;
    }
    s += __shfl_xor_sync(0xffffffffu, s, 1);
    s += __shfl_xor_sync(0xffffffffu, s, 2);
    float mu = s * (1.0f/128.0f);
    float q = 0.f;
#pragma unroll
    for (int j = 0; j < 32; j++) { float d = v[j]-mu; q += d*d; }
    q += __shfl_xor_sync(0xffffffffu, q, 1);
    q += __shfl_xor_sync(0xffffffffu, q, 2);
    float rstd = rsqrtf(q * (1.0f/128.0f) + LN_EPS);
#pragma unroll
    for (int j = 0; j < 32; j++) {
        int c = sub*32 + j;
        Xs2[r*132 + c] = pack2dup((v[j]-mu)*rstd*__ldg(gam+c) + __ldg(bet+c));
    }
}

#define GEMM_SMEM (64*132*8)

// Q,K,V in one pass: LN tile once, 3 weight passes (+att_bias scalar)
__global__ void __launch_bounds__(256) gemm_qkv_ln_kernel(
        const float* __restrict__ X,
        const float* __restrict__ gam, const float* __restrict__ bet,
        const float* __restrict__ attb,
        float* __restrict__ Q, float* __restrict__ K, float* __restrict__ V) {
    extern __shared__ char smc[];
    u64* Xs2 = (u64*)smc;
    int tid = threadIdx.x;
    int row0 = blockIdx.x * 64;
    ln_tile_load(X, gam, bet, Xs2, row0, tid);
    __syncthreads();
    int ty = tid >> 4, tx = tid & 15;
    int r0 = ty*4, c0 = tx*8;
    float sc = __ldg(attb);
    float acc[4][8];

    const float* Ws[3] = {g_wq, g_wk, g_wv};
    float* Ys[3] = {Q, K, V};
#pragma unroll
    for (int m = 0; m < 3; m++) {
        gemm_tile2(Xs2, Ws[m], r0, c0, acc);
#pragma unroll
        for (int i = 0; i < 4; i++) {
            int row = row0 + r0 + i;
#pragma unroll
            for (int j = 0; j < 8; j++)
                Ys[m][(size_t)row*DD + c0 + j] = acc[i][j] + sc;
        }
    }
}

// LN + GEMM, relu + bias (FFN first layer)
__global__ void __launch_bounds__(256) gemm_ln_relu_kernel(
        const float* __restrict__ X,
        const float* __restrict__ gam, const float* __restrict__ bet,
        const float* __restrict__ W, const float* __restrict__ bias,
        float* __restrict__ Y) {
    extern __shared__ char smc[];
    u64* Xs2 = (u64*)smc;
    int tid = threadIdx.x;
    int row0 = blockIdx.x * 64;
    ln_tile_load(X, gam, bet, Xs2, row0, tid);
    __syncthreads();
    int ty = tid >> 4, tx = tid & 15;
    int r0 = ty*4, c0 = tx*8;
    float acc[4][8];
    gemm_tile2(Xs2, W, r0, c0, acc);
    float bv[8];
#pragma unroll
    for (int j = 0; j < 8; j++) bv[j] = __ldg(bias + c0 + j);
#pragma unroll
    for (int i = 0; i < 4; i++) {
        int row = row0 + r0 + i;
#pragma unroll
        for (int j = 0; j < 8; j++)
            Y[(size_t)row*DD + c0 + j] = fmaxf(acc[i][j] + bv[j], 0.f);
    }
}

// Plain GEMM: Y = X@W + bias? + scalar? + resid?
__global__ void __launch_bounds__(256) gemm_kernel(
        const float* __restrict__ X, const float* __restrict__ W,
        float* __restrict__ Y,
        const float* __restrict__ bias, const float* __restrict__ resid,
        const float* __restrict__ scalar_ptr) {
    extern __shared__ char smc[];
    u64* Xs2 = (u64*)smc;
    int tid = threadIdx.x;
    int row0 = blockIdx.x * 64;
#pragma unroll
    for (int i = 0; i < 32; i++) {
        int li = tid + i*256;
        int r = li >> 7, c = li & 127;
        Xs2[r*132 + c] = pack2dup(X[(size_t)(row0 + r)*DD + c]);
    }
    __syncthreads();
    int ty = tid >> 4, tx = tid & 15;
    int r0 = ty*4, c0 = tx*8;
    float acc[4][8];
    gemm_tile2(Xs2, W, r0, c0, acc);
    float sc = scalar_ptr ? __ldg(scalar_ptr) : 0.f;
    float bv[8];
#pragma unroll
    for (int j = 0; j < 8; j++) bv[j] = bias ? __ldg(bias + c0 + j) : 0.f;
#pragma unroll
    for (int i = 0; i < 4; i++) {
        int row = row0 + r0 + i;
#pragma unroll
        for (int j = 0; j < 8; j++) {
            float v = acc[i][j] + sc + bv[j];
            if (resid) v += resid[(size_t)row*DD + c0 + j];
            Y[(size_t)row*DD + c0 + j] = v;
        }
    }
}

// ---------------------------------------------------------------------------
// Attention: one block per (b,h); 512 threads = 1 thread per query.
// Tiled online softmax (16 keys per tile) + f32x2 packed math.
// K/V reads are warp-uniform -> LDS broadcast (no conflicts).
// ---------------------------------------------------------------------------
#define KT 16
__global__ void __launch_bounds__(512) attn_kernel(const float* __restrict__ Q,
                                                   const float* __restrict__ Kg,
                                                   const float* __restrict__ Vg,
                                                   const int* __restrict__ mask,
                                                   float* __restrict__ Out) {
    extern __shared__ float sm[];
    float* Ksm = sm;                 // 512*16
    float* Vsm = sm + SS*DK;         // 512*16
    float* Msm = sm + 2*SS*DK;       // 512 additive mask bias

    int b = blockIdx.x >> 3;
    int h = blockIdx.x & 7;
    int tid = threadIdx.x;

    for (int i = tid; i < SS*DK; i += 512) {
        int t = i >> 4, kk = i & 15;
        size_t gi = ((size_t)(b*SS + t))*DD + h*DK + kk;
        Ksm[i] = Kg[gi];
        Vsm[i] = Vg[gi];
    }
    Msm[tid] = mask[b*SS + tid] ? 0.f : -1e30f;
    __syncthreads();

    // packed query
    u64 q2[8];
    {
        const float4* qp = (const float4*)(Q + ((size_t)(b*SS + tid))*DD + h*DK);
#pragma unroll
        for (int j = 0; j < 4; j++) {
            float4 t4 = qp[j];
            q2[2*j+0] = pack2(t4.x, t4.y);
            q2[2*j+1] = pack2(t4.z, t4.w);
        }
    }

    float mval = -1e30f, lsum = 0.f;
    u64 a2[8];
#pragma unroll
    for (int j = 0; j < 8; j++) a2[j] = 0ull;

    for (int tile = 0; tile < SS/KT; tile++) {
        const ulonglong2* Kp = (const ulonglong2*)(Ksm + tile*KT*DK);
        float scv[KT];
        float tmax = -1e30f;
#pragma unroll
        for (int tt = 0; tt < KT; tt++) {
            ulonglong2 k0 = Kp[tt*4+0], k1 = Kp[tt*4+1];
            ulonglong2 k2 = Kp[tt*4+2], k3 = Kp[tt*4+3];
            u64 s2 = mul2(q2[0], k0.x);
            s2 = fma2(q2[1], k0.y, s2);
            s2 = fma2(q2[2], k1.x, s2);
            s2 = fma2(q2[3], k1.y, s2);
            s2 = fma2(q2[4], k2.x, s2);
            s2 = fma2(q2[5], k2.y, s2);
            s2 = fma2(q2[6], k3.x, s2);
            s2 = fma2(q2[7], k3.y, s2);
            float2 sv = unpack2(s2);
            float s = fmaf(sv.x + sv.y, 0.25f, Msm[tile*KT + tt]);
            scv[tt] = s;
            tmax = fmaxf(tmax, s);
        }
        float mnew = fmaxf(mval, tmax);
        float corr = __expf(mval - mnew);
        mval = mnew;
        float psum = 0.f;
#pragma unroll
        for (int tt = 0; tt < KT; tt++) {
            float p = __expf(scv[tt] - mnew);
            scv[tt] = p;
            psum += p;
        }
        lsum = fmaf(lsum, corr, psum);
        u64 c2 = pack2dup(corr);
#pragma unroll
        for (int j = 0; j < 8; j++) a2[j] = mul2(a2[j], c2);
        const ulonglong2* Vp = (const ulonglong2*)(Vsm + tile*KT*DK);
#pragma unroll
        for (int tt = 0; tt < KT; tt++) {
            u64 pp = pack2dup(scv[tt]);
            ulonglong2 v0 = Vp[tt*4+0], v1 = Vp[tt*4+1];
            ulonglong2 v2 = Vp[tt*4+2], v3 = Vp[tt*4+3];
            a2[0] = fma2(pp, v0.x, a2[0]);
            a2[1] = fma2(pp, v0.y, a2[1]);
            a2[2] = fma2(pp, v1.x, a2[2]);
            a2[3] = fma2(pp, v1.y, a2[3]);
            a2[4] = fma2(pp, v2.x, a2[4]);
            a2[5] = fma2(pp, v2.y, a2[5]);
            a2[6] = fma2(pp, v3.x, a2[6]);
            a2[7] = fma2(pp, v3.y, a2[7]);
        }
    }
    float inv_l = 1.0f / lsum;
    float* op = Out + ((size_t)(b*SS + tid))*DD + h*DK;
#pragma unroll
    for (int j = 0; j < 8; j++) {
        float2 t = unpack2(a2[j]);
        op[2*j+0] = t.x * inv_l;
        op[2*j+1] = t.y * inv_l;
    }
}

// ---------------------------------------------------------------------------
// Host launcher
// ---------------------------------------------------------------------------
extern "C" void kernel_launch(void* const* d_in, const int* in_sizes, int n_in,
                              void* d_out, int out_size) {
    const float* x     = (const float*)d_in[0];
    const int*   mask  = (const int*)  d_in[1];
    const float* ln_s  = (const float*)d_in[2];
    const float* ln_b  = (const float*)d_in[3];
    const float* dw_w  = (const float*)d_in[4];
    const float* dw_b  = (const float*)d_in[5];
    const float* pw_w  = (const float*)d_in[6];
    const float* pw_b  = (const float*)d_in[7];
    const float* Wq    = (const float*)d_in[8];
    const float* Wk    = (const float*)d_in[9];
    const float* Wv    = (const float*)d_in[10];
    const float* Wo    = (const float*)d_in[11];
    const float* attb  = (const float*)d_in[12];
    const float* f1w   = (const float*)d_in[13];
    const float* f1b   = (const float*)d_in[14];
    const float* f2w   = (const float*)d_in[15];
    const float* f2b   = (const float*)d_in[16];
    float* out = (float*)d_out;

    float *p_a, *p_b, *p_q, *p_k, *p_v, *p_t, *p_wpw, *p_wf1, *p_wf2;
    cudaGetSymbolAddress((void**)&p_a,   g_a);
    cudaGetSymbolAddress((void**)&p_b,   g_b);
    cudaGetSymbolAddress((void**)&p_q,   g_q);
    cudaGetSymbolAddress((void**)&p_k,   g_k);
    cudaGetSymbolAddress((void**)&p_v,   g_v);
    cudaGetSymbolAddress((void**)&p_t,   g_t);
    cudaGetSymbolAddress((void**)&p_wpw, g_wpw);
    cudaGetSymbolAddress((void**)&p_wf1, g_wf1);
    cudaGetSymbolAddress((void**)&p_wf2, g_wf2);

    const int attn_smem = (2*SS*DK + SS) * (int)sizeof(float);  // 67.6 KB
    cudaFuncSetAttribute(conv_fused_kernel, cudaFuncAttributeMaxDynamicSharedMemorySize, CONV_SMEM);
    cudaFuncSetAttribute(attn_kernel, cudaFuncAttributeMaxDynamicSharedMemorySize, attn_smem);
    cudaFuncSetAttribute(gemm_qkv_ln_kernel, cudaFuncAttributeMaxDynamicSharedMemorySize, GEMM_SMEM);
    cudaFuncSetAttribute(gemm_ln_relu_kernel, cudaFuncAttributeMaxDynamicSharedMemorySize, GEMM_SMEM);
    cudaFuncSetAttribute(gemm_kernel, cudaFuncAttributeMaxDynamicSharedMemorySize, GEMM_SMEM);

    // weight repacks (one kernel)
    repack_all_kernel<<<(NC*DD*DD + 255)/256, 256>>>(Wq, Wk, Wv, pw_w, f1w, f2w);

    // 4 fused conv blocks; conv0 fuses the positional-signal add and reads x.
    // chain: x -> g_b -> g_a -> g_b -> g_a
    conv_fused_kernel<<<NTOK/64, 256, CONV_SMEM>>>(
        x, ln_s + 0*DD, ln_b + 0*DD, dw_w + 0*DD*KK, dw_b + 0*DD,
        p_wpw + 0*DD*DD, pw_b + 0*DD, p_b, 1);
    float* bufs[2] = {p_b, p_a};
    for (int i = 1; i < NC; i++) {
        conv_fused_kernel<<<NTOK/64, 256, CONV_SMEM>>>(
            bufs[(i + 1) & 1], ln_s + i*DD, ln_b + i*DD,
            dw_w + i*DD*KK, dw_b + i*DD,
            p_wpw + i*DD*DD, pw_b + i*DD,
            bufs[i & 1], 0);
    }
    float* cur = p_a;   // after 4 convs

    // attention: fused LN + QKV
    gemm_qkv_ln_kernel<<<NTOK/64, 256, GEMM_SMEM>>>(cur, ln_s + NC*DD, ln_b + NC*DD,
                                                    attb, p_q, p_k, p_v);
    attn_kernel<<<BB*HH, 512, attn_smem>>>(p_q, p_k, p_v, mask, p_t);
    // out = mh @ Wo + b0 + residual(cur)
    gemm_kernel<<<NTOK/64, 256, GEMM_SMEM>>>(p_t, Wo, cur, nullptr, cur, attb);

    // feed-forward: LN+f1(relu) -> f2 (+resid) -> d_out
    gemm_ln_relu_kernel<<<NTOK/64, 256, GEMM_SMEM>>>(cur, ln_s + (NC+1)*DD, ln_b + (NC+1)*DD,
                                                     p_wf1, f1b, p_t);
    gemm_kernel<<<NTOK/64, 256, GEMM_SMEM>>>(p_t, p_wf2, out, f2b, cur, nullptr);

    (void)in_sizes; (void)n_in; (void)out_size;
}